// round 13
// baseline (speedup 1.0000x reference)
#include <cuda_runtime.h>
#include <math.h>

#define PI_F 3.14159265358979323846f
#define IPB 4   // images per FC block

__device__ float g_feat[128 * 784];   // patch features, [image][patch*4+q]

// ---------------- K1: circuit -> features (proven R12 code) ----------------
// grid 196 x 128 threads; thread = one patch.
__global__ __launch_bounds__(128, 2) void circuit_kernel(
    const float* __restrict__ x,      // [128,1,28,28]
    const float* __restrict__ weight) // [60]
{
    __shared__ float4 ssu2[20];
    __shared__ float2 C2[16][16];

    const int t = threadIdx.x;

    if (t < 20) {
        const int layer = t >> 2, q = t & 3;
        const int base = layer * 12;
        float sa, ca, sb, cb, sc, cc;
        __sincosf(0.5f * weight[base + q],     &sa, &ca);
        __sincosf(0.5f * weight[base + 4 + q], &sb, &cb);
        __sincosf(0.5f * weight[base + 8 + q], &sc, &cc);
        ssu2[t] = make_float4( cb * (cc * ca - sc * sa),
                              -sb * (cc * ca + sc * sa),
                               cb * (sc * ca + cc * sa),
                               sb * (cc * sa - sc * ca));
    }

    const int p = blockIdx.x * 128 + t;     // 0..25087
    const int img = p / 196;
    const int pp  = p - img * 196;
    const float* xb = x + img * 784 + (pp / 14) * 56 + (pp % 14) * 2;
    const float px0 = xb[0], px1 = xb[1], px2 = xb[28], px3 = xb[29];
    __syncthreads();   // ssu2 ready

    // ---- Phase A: build C (2 columns per thread) ----
    {
        const int i  = t & 15;
        const int jA = t >> 4;
        const int jB = jA + 8;

        float arv[2], aiv[2];
        #pragma unroll
        for (int h = 0; h < 2; h++) {
            const int j = h ? jB : jA;
            float rr = 1.f, ii = 0.f;
            #pragma unroll
            for (int q = 0; q < 4; q++) {
                const float4 u = ssu2[q];
                const int jb = (j >> (3 - q)) & 1, ib = (i >> (3 - q)) & 1;
                float wr, wi;
                if (!jb) { wr = ib ?  u.z : u.x;  wi = ib ?  u.w : u.y; }
                else     { wr = ib ? -u.y : u.w;  wi = ib ? -u.x : u.z; }
                const float nr = rr * wr - ii * wi;
                ii = rr * wi + ii * wr;
                rr = nr;
            }
            arv[h] = rr; aiv[h] = ii;
        }

        #pragma unroll
        for (int layer = 1; layer < 5; layer++) {
            #pragma unroll
            for (int q = 0; q < 4; q++) {
                const int cb = 8 >> q, tb = 8 >> ((q + 1) & 3);
                #pragma unroll
                for (int h = 0; h < 2; h++) {
                    const float pr  = __shfl_xor_sync(0xffffffffu, arv[h], tb);
                    const float pi2 = __shfl_xor_sync(0xffffffffu, aiv[h], tb);
                    if (i & cb) { arv[h] = pr; aiv[h] = pi2; }
                }
            }
            #pragma unroll
            for (int q = 0; q < 4; q++) {
                const float4 u = ssu2[layer * 4 + q];
                const int st = 8 >> q;
                const bool hi = (i & st) != 0;
                const float ys = hi ? u.y : -u.y;
                const float zs = hi ? u.z : -u.z;
                #pragma unroll
                for (int h = 0; h < 2; h++) {
                    const float pr  = __shfl_xor_sync(0xffffffffu, arv[h], st);
                    const float pi2 = __shfl_xor_sync(0xffffffffu, aiv[h], st);
                    const float nr = u.x * arv[h] + ys * aiv[h] + zs * pr  - u.w * pi2;
                    const float ni = u.x * aiv[h] - ys * arv[h] + zs * pi2 + u.w * pr;
                    arv[h] = nr; aiv[h] = ni;
                }
            }
        }
        C2[i][jA] = make_float2(arv[0], aiv[0]);
        C2[i][jB] = make_float2(arv[1], aiv[1]);
    }
    __syncthreads();   // C ready

    // ---- Phase B: per-patch m + C*m + expectations ----
    {
        float c0, s0, c1, s1, c2, s2, c3, s3;
        __sincosf(PI_F * px0, &s0, &c0);
        __sincosf(PI_F * px1, &s1, &c1);
        __sincosf(PI_F * px2, &s2, &c2);
        __sincosf(PI_F * px3, &s3, &c3);
        float m01[4], m23[4];
        m01[0] = c0 * c1; m01[1] = c0 * s1; m01[2] = s0 * c1; m01[3] = s0 * s1;
        m23[0] = c2 * c3; m23[1] = c2 * s3; m23[2] = s2 * c3; m23[3] = s2 * s3;
        float m[16];
        #pragma unroll
        for (int j = 0; j < 16; j++) m[j] = m01[j >> 2] * m23[j & 3];

        float pr[16];
        #pragma unroll
        for (int i = 0; i < 16; i++) {
            const float4* crow = (const float4*)&C2[i][0];
            float accr = 0.f, acci = 0.f;
            #pragma unroll
            for (int jj = 0; jj < 8; jj++) {
                const float4 cc = crow[jj];
                accr += cc.x * m[2 * jj] + cc.z * m[2 * jj + 1];
                acci += cc.y * m[2 * jj] + cc.w * m[2 * jj + 1];
            }
            pr[i] = accr * accr + acci * acci;
        }

        float e[4];
        #pragma unroll
        for (int q = 0; q < 4; q++) {
            const int st = 8 >> q;
            float acc = 0.f;
            #pragma unroll
            for (int i = 0; i < 16; i++) acc += (i & st) ? -pr[i] : pr[i];
            e[q] = acc;
        }
        *(float4*)&g_feat[img * 784 + pp * 4] = make_float4(e[0], e[1], e[2], e[3]);
    }
}

// ---------------- K2: FC head, coalesced, 4 images per block ----------------
// grid 32 x 256 threads (8 warps). Warp w computes outputs w*8..w*8+7; lanes
// split each 784-long weight row contiguously (float4 idx = r*32+lane ->
// 4 wavefronts/LDG instead of 32). Each weight load is reused for 4 images.
__global__ __launch_bounds__(256, 1) void fc_kernel(
    const float* __restrict__ fc1_w,  // [64,784]
    const float* __restrict__ fc1_b,  // [64]
    const float* __restrict__ fc2_w,  // [10,64]
    const float* __restrict__ fc2_b,  // [10]
    float* __restrict__ out)          // [128,10]
{
    __shared__ float sfeat[IPB][784];
    __shared__ float sh[IPB][64];

    const int t = threadIdx.x;
    const int b = blockIdx.x;         // 0..31

    // Coalesced feature load: IPB*196 float4
    #pragma unroll
    for (int i = t; i < IPB * 196; i += 256) {
        const int im = i / 196, idx = i - im * 196;
        ((float4*)sfeat[im])[idx] =
            ((const float4*)(g_feat + (b * IPB + im) * 784))[idx];
    }
    __syncthreads();

    const int w = t >> 5, lane = t & 31;
    #pragma unroll 1
    for (int oo = 0; oo < 8; oo++) {
        const int o = w * 8 + oo;
        const float4* wrow = (const float4*)(fc1_w + o * 784);
        float acc0 = 0.f, acc1 = 0.f, acc2 = 0.f, acc3 = 0.f;
        #pragma unroll
        for (int r = 0; r < 7; r++) {
            const int idx = r * 32 + lane;
            if (idx < 196) {
                const float4 w4 = wrow[idx];
                float4 f;
                f = ((const float4*)sfeat[0])[idx];
                acc0 += w4.x * f.x + w4.y * f.y + w4.z * f.z + w4.w * f.w;
                f = ((const float4*)sfeat[1])[idx];
                acc1 += w4.x * f.x + w4.y * f.y + w4.z * f.z + w4.w * f.w;
                f = ((const float4*)sfeat[2])[idx];
                acc2 += w4.x * f.x + w4.y * f.y + w4.z * f.z + w4.w * f.w;
                f = ((const float4*)sfeat[3])[idx];
                acc3 += w4.x * f.x + w4.y * f.y + w4.z * f.z + w4.w * f.w;
            }
        }
        float a[IPB] = {acc0, acc1, acc2, acc3};
        #pragma unroll
        for (int im = 0; im < IPB; im++) {
            float s = a[im];
            s += __shfl_xor_sync(0xffffffffu, s, 16);
            s += __shfl_xor_sync(0xffffffffu, s, 8);
            s += __shfl_xor_sync(0xffffffffu, s, 4);
            s += __shfl_xor_sync(0xffffffffu, s, 2);
            s += __shfl_xor_sync(0xffffffffu, s, 1);
            if (lane == 0) sh[im][o] = fmaxf(s + fc1_b[o], 0.f);
        }
    }
    __syncthreads();

    // FC2: IPB*10 outputs
    if (t < IPB * 10) {
        const int im = t / 10, o = t - im * 10;
        float sum = fc2_b[o];
        const float* w2 = fc2_w + o * 64;
        #pragma unroll
        for (int k = 0; k < 64; k++) sum += w2[k] * sh[im][k];
        out[(b * IPB + im) * 10 + o] = sum;
    }
}

extern "C" void kernel_launch(void* const* d_in, const int* in_sizes, int n_in,
                              void* d_out, int out_size) {
    const float* x      = (const float*)d_in[0];
    const float* weight = (const float*)d_in[1];
    const float* fc1_w  = (const float*)d_in[2];
    const float* fc1_b  = (const float*)d_in[3];
    const float* fc2_w  = (const float*)d_in[4];
    const float* fc2_b  = (const float*)d_in[5];
    float* out = (float*)d_out;

    circuit_kernel<<<196, 128>>>(x, weight);
    fc_kernel<<<128 / IPB, 256>>>(fc1_w, fc1_b, fc2_w, fc2_b, out);
}

// round 14
// speedup vs baseline: 1.1629x; 1.1629x over previous
#include <cuda_runtime.h>
#include <math.h>

#define PI_F 3.14159265358979323846f
#define IPB 2   // images per FC block

__device__ float g_feat[128 * 784];   // patch features, [image][patch*4+q]

// ---------------- K1: circuit -> features (proven R12/R13 code) ----------------
// grid 196 x 128 threads; thread = one patch.
__global__ __launch_bounds__(128, 2) void circuit_kernel(
    const float* __restrict__ x,      // [128,1,28,28]
    const float* __restrict__ weight) // [60]
{
    __shared__ float4 ssu2[20];
    __shared__ float2 C2[16][16];

    const int t = threadIdx.x;

    if (t < 20) {
        const int layer = t >> 2, q = t & 3;
        const int base = layer * 12;
        float sa, ca, sb, cb, sc, cc;
        __sincosf(0.5f * weight[base + q],     &sa, &ca);
        __sincosf(0.5f * weight[base + 4 + q], &sb, &cb);
        __sincosf(0.5f * weight[base + 8 + q], &sc, &cc);
        ssu2[t] = make_float4( cb * (cc * ca - sc * sa),
                              -sb * (cc * ca + sc * sa),
                               cb * (sc * ca + cc * sa),
                               sb * (cc * sa - sc * ca));
    }

    const int p = blockIdx.x * 128 + t;     // 0..25087
    const int img = p / 196;
    const int pp  = p - img * 196;
    const float* xb = x + img * 784 + (pp / 14) * 56 + (pp % 14) * 2;
    const float px0 = xb[0], px1 = xb[1], px2 = xb[28], px3 = xb[29];
    __syncthreads();   // ssu2 ready

    // ---- Phase A: build C (2 columns per thread) ----
    {
        const int i  = t & 15;
        const int jA = t >> 4;
        const int jB = jA + 8;

        float arv[2], aiv[2];
        #pragma unroll
        for (int h = 0; h < 2; h++) {
            const int j = h ? jB : jA;
            float rr = 1.f, ii = 0.f;
            #pragma unroll
            for (int q = 0; q < 4; q++) {
                const float4 u = ssu2[q];
                const int jb = (j >> (3 - q)) & 1, ib = (i >> (3 - q)) & 1;
                float wr, wi;
                if (!jb) { wr = ib ?  u.z : u.x;  wi = ib ?  u.w : u.y; }
                else     { wr = ib ? -u.y : u.w;  wi = ib ? -u.x : u.z; }
                const float nr = rr * wr - ii * wi;
                ii = rr * wi + ii * wr;
                rr = nr;
            }
            arv[h] = rr; aiv[h] = ii;
        }

        #pragma unroll
        for (int layer = 1; layer < 5; layer++) {
            #pragma unroll
            for (int q = 0; q < 4; q++) {
                const int cb = 8 >> q, tb = 8 >> ((q + 1) & 3);
                #pragma unroll
                for (int h = 0; h < 2; h++) {
                    const float pr  = __shfl_xor_sync(0xffffffffu, arv[h], tb);
                    const float pi2 = __shfl_xor_sync(0xffffffffu, aiv[h], tb);
                    if (i & cb) { arv[h] = pr; aiv[h] = pi2; }
                }
            }
            #pragma unroll
            for (int q = 0; q < 4; q++) {
                const float4 u = ssu2[layer * 4 + q];
                const int st = 8 >> q;
                const bool hi = (i & st) != 0;
                const float ys = hi ? u.y : -u.y;
                const float zs = hi ? u.z : -u.z;
                #pragma unroll
                for (int h = 0; h < 2; h++) {
                    const float pr  = __shfl_xor_sync(0xffffffffu, arv[h], st);
                    const float pi2 = __shfl_xor_sync(0xffffffffu, aiv[h], st);
                    const float nr = u.x * arv[h] + ys * aiv[h] + zs * pr  - u.w * pi2;
                    const float ni = u.x * aiv[h] - ys * arv[h] + zs * pi2 + u.w * pr;
                    arv[h] = nr; aiv[h] = ni;
                }
            }
        }
        C2[i][jA] = make_float2(arv[0], aiv[0]);
        C2[i][jB] = make_float2(arv[1], aiv[1]);
    }
    __syncthreads();   // C ready

    // ---- Phase B: per-patch m + C*m + expectations ----
    {
        float c0, s0, c1, s1, c2, s2, c3, s3;
        __sincosf(PI_F * px0, &s0, &c0);
        __sincosf(PI_F * px1, &s1, &c1);
        __sincosf(PI_F * px2, &s2, &c2);
        __sincosf(PI_F * px3, &s3, &c3);
        float m01[4], m23[4];
        m01[0] = c0 * c1; m01[1] = c0 * s1; m01[2] = s0 * c1; m01[3] = s0 * s1;
        m23[0] = c2 * c3; m23[1] = c2 * s3; m23[2] = s2 * c3; m23[3] = s2 * s3;
        float m[16];
        #pragma unroll
        for (int j = 0; j < 16; j++) m[j] = m01[j >> 2] * m23[j & 3];

        float pr[16];
        #pragma unroll
        for (int i = 0; i < 16; i++) {
            const float4* crow = (const float4*)&C2[i][0];
            float accr = 0.f, acci = 0.f;
            #pragma unroll
            for (int jj = 0; jj < 8; jj++) {
                const float4 cc = crow[jj];
                accr += cc.x * m[2 * jj] + cc.z * m[2 * jj + 1];
                acci += cc.y * m[2 * jj] + cc.w * m[2 * jj + 1];
            }
            pr[i] = accr * accr + acci * acci;
        }

        float e[4];
        #pragma unroll
        for (int q = 0; q < 4; q++) {
            const int st = 8 >> q;
            float acc = 0.f;
            #pragma unroll
            for (int i = 0; i < 16; i++) acc += (i & st) ? -pr[i] : pr[i];
            e[q] = acc;
        }
        *(float4*)&g_feat[img * 784 + pp * 4] = make_float4(e[0], e[1], e[2], e[3]);
    }
}

// ---------------- K2: FC head ----------------
// grid 64 x 256 threads (8 warps), IPB=2 images/block. Warp w computes outputs
// 8w..8w+7; lanes split each weight row contiguously (float4 idx = r*32+lane,
// 4 wavefronts/LDG). oo loop FULLY UNROLLED: all 56 LDGs independent and in
// flight, 16 independent 5-deep shfl-reduce chains pipeline instead of
// serializing. Weight loads reused across both images.
__global__ __launch_bounds__(256, 1) void fc_kernel(
    const float* __restrict__ fc1_w,  // [64,784]
    const float* __restrict__ fc1_b,  // [64]
    const float* __restrict__ fc2_w,  // [10,64]
    const float* __restrict__ fc2_b,  // [10]
    float* __restrict__ out)          // [128,10]
{
    __shared__ float sfeat[IPB][784];
    __shared__ float sh[IPB][64];

    const int t = threadIdx.x;
    const int b = blockIdx.x;         // 0..63

    // Coalesced feature load: IPB*196 float4
    for (int i = t; i < IPB * 196; i += 256) {
        const int im = i / 196, idx = i - im * 196;
        ((float4*)sfeat[im])[idx] =
            ((const float4*)(g_feat + (b * IPB + im) * 784))[idx];
    }
    __syncthreads();

    const int w = t >> 5, lane = t & 31;
    float r0[8], r1[8];               // acc per output, per image

    #pragma unroll
    for (int oo = 0; oo < 8; oo++) {
        const int o = w * 8 + oo;
        const float4* wrow = (const float4*)(fc1_w + o * 784);
        float a0 = 0.f, a1 = 0.f;
        #pragma unroll
        for (int r = 0; r < 7; r++) {
            const int idx = r * 32 + lane;
            if (idx < 196) {
                const float4 w4 = __ldg(&wrow[idx]);
                float4 f;
                f = ((const float4*)sfeat[0])[idx];
                a0 += w4.x * f.x + w4.y * f.y + w4.z * f.z + w4.w * f.w;
                f = ((const float4*)sfeat[1])[idx];
                a1 += w4.x * f.x + w4.y * f.y + w4.z * f.z + w4.w * f.w;
            }
        }
        r0[oo] = a0; r1[oo] = a1;
    }

    // 16 independent butterfly reductions (pipeline across oo/im)
    #pragma unroll
    for (int oo = 0; oo < 8; oo++) {
        #pragma unroll
        for (int d = 16; d >= 1; d >>= 1) {
            r0[oo] += __shfl_xor_sync(0xffffffffu, r0[oo], d);
            r1[oo] += __shfl_xor_sync(0xffffffffu, r1[oo], d);
        }
        if (lane == 0) {
            const int o = w * 8 + oo;
            sh[0][o] = fmaxf(r0[oo] + fc1_b[o], 0.f);
            sh[1][o] = fmaxf(r1[oo] + fc1_b[o], 0.f);
        }
    }
    __syncthreads();

    // FC2: IPB*10 outputs
    if (t < IPB * 10) {
        const int im = t / 10, o = t - im * 10;
        float sum = fc2_b[o];
        const float* w2 = fc2_w + o * 64;
        #pragma unroll
        for (int k = 0; k < 64; k++) sum += w2[k] * sh[im][k];
        out[(b * IPB + im) * 10 + o] = sum;
    }
}

extern "C" void kernel_launch(void* const* d_in, const int* in_sizes, int n_in,
                              void* d_out, int out_size) {
    const float* x      = (const float*)d_in[0];
    const float* weight = (const float*)d_in[1];
    const float* fc1_w  = (const float*)d_in[2];
    const float* fc1_b  = (const float*)d_in[3];
    const float* fc2_w  = (const float*)d_in[4];
    const float* fc2_b  = (const float*)d_in[5];
    float* out = (float*)d_out;

    circuit_kernel<<<196, 128>>>(x, weight);
    fc_kernel<<<128 / IPB, 256>>>(fc1_w, fc1_b, fc2_w, fc2_b, out);
}

// round 15
// speedup vs baseline: 1.3810x; 1.1875x over previous
#include <cuda_runtime.h>
#include <math.h>

#define PI_F 3.14159265358979323846f

// Fused single kernel: 128 blocks (one per image) x 256 threads.
// Phase A: all 256 threads build the 16x16 complex circuit matrix C
//          cooperatively (thread (j=t>>4, i=t&15); proven R9 code).
// Phase B: threads 0..195 compute per-patch m (real 16-vec), C*m, |.|^2,
//          <Z_q> -> sfeat[784] in smem.
// Phase C: FC1 with R14 coalesced layout (warp w -> outputs 8w..8w+7, lanes
//          split the 196 float4 row contiguously), relu; FC2.
__global__ __launch_bounds__(256, 1) void qnet_kernel(
    const float* __restrict__ x,      // [128,1,28,28]
    const float* __restrict__ weight, // [60]
    const float* __restrict__ fc1_w,  // [64,784]
    const float* __restrict__ fc1_b,  // [64]
    const float* __restrict__ fc2_w,  // [10,64]
    const float* __restrict__ fc2_b,  // [10]
    float* __restrict__ out)          // [128,10]
{
    __shared__ float4 ssu2[20];
    __shared__ float2 C2[16][16];
    __shared__ float sfeat[784];
    __shared__ float sh[64];

    const int t = threadIdx.x;
    const int b = blockIdx.x;

    // U = Ry(c)*Rz(bb)*Ry(a) = [[alpha, -conj(beta)],[beta, conj(alpha)]]
    if (t < 20) {
        const int layer = t >> 2, q = t & 3;
        const int base = layer * 12;
        float sa, ca, sb, cb, sc, cc;
        __sincosf(0.5f * weight[base + q],     &sa, &ca);
        __sincosf(0.5f * weight[base + 4 + q], &sb, &cb);
        __sincosf(0.5f * weight[base + 8 + q], &sc, &cc);
        ssu2[t] = make_float4( cb * (cc * ca - sc * sa),
                              -sb * (cc * ca + sc * sa),
                               cb * (sc * ca + cc * sa),
                               sb * (cc * sa - sc * ca));
    }

    // Early x loads (consumed in phase B; DRAM latency hides under phase A).
    float px0, px1, px2, px3;
    if (t < 196) {
        const int pi_ = t / 14, pj = t % 14;
        const float* xb = x + b * 784 + (2 * pi_) * 28 + 2 * pj;
        px0 = xb[0]; px1 = xb[1]; px2 = xb[28]; px3 = xb[29];
    }
    __syncthreads();   // ssu2 ready

    // ---- Phase A: build C (all 256 threads, one amplitude each) ----
    {
        const int j = t >> 4;         // column
        const int i = t & 15;         // amplitude index (q0=bit3 .. q3=bit0)

        float arv = 1.f, aiv = 0.f;
        #pragma unroll
        for (int q = 0; q < 4; q++) {
            const float4 u = ssu2[q];
            const int jb = (j >> (3 - q)) & 1, ib = (i >> (3 - q)) & 1;
            float wr, wi;
            if (!jb) { wr = ib ?  u.z : u.x;  wi = ib ?  u.w : u.y; }
            else     { wr = ib ? -u.y : u.w;  wi = ib ? -u.x : u.z; }
            const float nr = arv * wr - aiv * wi;
            aiv = arv * wi + aiv * wr;
            arv = nr;
        }

        #pragma unroll
        for (int layer = 1; layer < 5; layer++) {
            // CNOT ring 0->1->2->3->0: conditional partner take
            #pragma unroll
            for (int q = 0; q < 4; q++) {
                const int cb = 8 >> q, tb = 8 >> ((q + 1) & 3);
                const float pr  = __shfl_xor_sync(0xffffffffu, arv, tb);
                const float pi2 = __shfl_xor_sync(0xffffffffu, aiv, tb);
                if (i & cb) { arv = pr; aiv = pi2; }
            }
            // Merged SU(2) per qubit: branch-free signed update
            #pragma unroll
            for (int q = 0; q < 4; q++) {
                const float4 u = ssu2[layer * 4 + q];
                const int st = 8 >> q;
                const float pr  = __shfl_xor_sync(0xffffffffu, arv, st);
                const float pi2 = __shfl_xor_sync(0xffffffffu, aiv, st);
                const bool hi = (i & st) != 0;
                const float ys = hi ? u.y : -u.y;
                const float zs = hi ? u.z : -u.z;
                const float nr = u.x * arv + ys * aiv + zs * pr  - u.w * pi2;
                const float ni = u.x * aiv - ys * arv + zs * pi2 + u.w * pr;
                arv = nr; aiv = ni;
            }
        }
        C2[i][j] = make_float2(arv, aiv);
    }
    __syncthreads();   // C ready

    // ---- Phase B: per-patch m + C*m + expectations ----
    if (t < 196) {
        float c0, s0, c1, s1, c2, s2, c3, s3;
        __sincosf(PI_F * px0, &s0, &c0);
        __sincosf(PI_F * px1, &s1, &c1);
        __sincosf(PI_F * px2, &s2, &c2);
        __sincosf(PI_F * px3, &s3, &c3);
        float m01[4], m23[4];
        m01[0] = c0 * c1; m01[1] = c0 * s1; m01[2] = s0 * c1; m01[3] = s0 * s1;
        m23[0] = c2 * c3; m23[1] = c2 * s3; m23[2] = s2 * c3; m23[3] = s2 * s3;
        float m[16];
        #pragma unroll
        for (int j = 0; j < 16; j++) m[j] = m01[j >> 2] * m23[j & 3];

        float p[16];
        #pragma unroll
        for (int i = 0; i < 16; i++) {
            const float4* crow = (const float4*)&C2[i][0];  // broadcast LDS.128
            float accr = 0.f, acci = 0.f;
            #pragma unroll
            for (int jj = 0; jj < 8; jj++) {
                const float4 cc = crow[jj];
                accr += cc.x * m[2 * jj] + cc.z * m[2 * jj + 1];
                acci += cc.y * m[2 * jj] + cc.w * m[2 * jj + 1];
            }
            p[i] = accr * accr + acci * acci;
        }

        float e[4];
        #pragma unroll
        for (int q = 0; q < 4; q++) {
            const int st = 8 >> q;
            float acc = 0.f;
            #pragma unroll
            for (int i = 0; i < 16; i++) acc += (i & st) ? -p[i] : p[i];
            e[q] = acc;
        }
        *(float4*)&sfeat[t * 4] = make_float4(e[0], e[1], e[2], e[3]);
    }
    __syncthreads();   // features ready

    // ---- Phase C: FC1 coalesced (warp w -> outputs 8w..8w+7) ----
    {
        const int w = t >> 5, lane = t & 31;
        float acc[8];

        #pragma unroll
        for (int oo = 0; oo < 8; oo++) {
            const int o = w * 8 + oo;
            const float4* wrow = (const float4*)(fc1_w + o * 784);
            float a = 0.f;
            #pragma unroll
            for (int r = 0; r < 7; r++) {
                const int idx = r * 32 + lane;
                if (idx < 196) {
                    const float4 w4 = __ldg(&wrow[idx]);
                    const float4 f = ((const float4*)sfeat)[idx];
                    a += w4.x * f.x + w4.y * f.y + w4.z * f.z + w4.w * f.w;
                }
            }
            acc[oo] = a;
        }

        // 8 independent 5-deep butterfly reductions (pipeline across oo)
        #pragma unroll
        for (int oo = 0; oo < 8; oo++) {
            #pragma unroll
            for (int d = 16; d >= 1; d >>= 1)
                acc[oo] += __shfl_xor_sync(0xffffffffu, acc[oo], d);
            if (lane == 0) {
                const int o = w * 8 + oo;
                sh[o] = fmaxf(acc[oo] + fc1_b[o], 0.f);
            }
        }
    }
    __syncthreads();

    // FC2: 10 outputs
    if (t < 10) {
        float sum = fc2_b[t];
        const float* w2 = fc2_w + t * 64;
        #pragma unroll
        for (int k = 0; k < 64; k++) sum += w2[k] * sh[k];
        out[b * 10 + t] = sum;
    }
}

extern "C" void kernel_launch(void* const* d_in, const int* in_sizes, int n_in,
                              void* d_out, int out_size) {
    const float* x      = (const float*)d_in[0];
    const float* weight = (const float*)d_in[1];
    const float* fc1_w  = (const float*)d_in[2];
    const float* fc1_b  = (const float*)d_in[3];
    const float* fc2_w  = (const float*)d_in[4];
    const float* fc2_b  = (const float*)d_in[5];
    float* out = (float*)d_out;

    const int B = in_sizes[0] / 784;  // 128
    qnet_kernel<<<B, 256>>>(x, weight, fc1_w, fc1_b, fc2_w, fc2_b, out);
}